// round 7
// baseline (speedup 1.0000x reference)
#include <cuda_runtime.h>
#include <cuda_fp16.h>
#include <math.h>
#include <stdint.h>

#define T_TOK   16384
#define H_DIM   2048
#define E_DIM   64
#define BM      64
#define KC      32
#define NSTG    (H_DIM / KC)            // 64
#define NBLK    (T_TOK / BM)            // 256
#define NTHR    128

#define W_OFF   0
#define I_OFF   32768
#define L_OFF   65536
#define Z_OFF   1114112
#define LB_OFF  1114113

#define PITCH   80                      // 64B (32 fp16) + 16B pad per k-row
#define ATILE   (BM * PITCH)            // 5120 B per A limb
#define BTILE   (E_DIM * PITCH)         // 5120 B per B limb
#define STG_B   (2 * ATILE + 2 * BTILE) // 20480 B per stage
#define DYN_B   (2 * STG_B)             // 40960 -> 3 CTAs/SM

__device__ float g_partials[NBLK * 3 * E_DIM];
__device__ int   g_done = 0;

__device__ __forceinline__ uint32_t smem_u32(const void* p) {
    uint32_t a;
    asm("{ .reg .u64 t; cvta.to.shared.u64 t, %1; cvt.u32.u64 %0, t; }" : "=r"(a) : "l"(p));
    return a;
}
__device__ __forceinline__ void sts64(uint32_t a, uint32_t x, uint32_t y) {
    asm volatile("st.shared.v2.b32 [%0], {%1, %2};" :: "r"(a), "r"(x), "r"(y));
}
#define LDSM_X4(r0, r1, r2, r3, addr)                                         \
    asm volatile("ldmatrix.sync.aligned.m8n8.x4.shared.b16 {%0,%1,%2,%3}, [%4];" \
                 : "=r"(r0), "=r"(r1), "=r"(r2), "=r"(r3) : "r"(addr))
#define MMA16816(d, a, b)                                                     \
    asm volatile("mma.sync.aligned.m16n8k16.row.col.f32.f16.f16.f32 "         \
                 "{%0,%1,%2,%3}, {%4,%5,%6,%7}, {%8,%9}, {%0,%1,%2,%3};"      \
                 : "+f"((d)[0]), "+f"((d)[1]), "+f"((d)[2]), "+f"((d)[3])     \
                 : "r"((a)[0]), "r"((a)[1]), "r"((a)[2]), "r"((a)[3]),        \
                   "r"((b)[0]), "r"((b)[1]))

// 2-limb fp16 split: h+m ~ x to 2^-22 rel; residual subtraction exact.
__device__ __forceinline__ void split2(float x0, float x1, uint32_t& h, uint32_t& m) {
    __half2 h2 = __floats2half2_rn(x0, x1);
    h = *reinterpret_cast<uint32_t*>(&h2);
    float2 hf = __half22float2(h2);
    __half2 m2 = __floats2half2_rn(x0 - hf.x, x1 - hf.y);
    m = *reinterpret_cast<uint32_t*>(&m2);
}

__global__ __launch_bounds__(NTHR, 3)
void fused_router_kernel(const float* __restrict__ A, const float* __restrict__ W,
                         float* __restrict__ out)
{
    extern __shared__ __align__(16) unsigned char dynsm[];
    const uint32_t sbase = smem_u32(dynsm);

    const int tid  = threadIdx.x;
    const int wid  = tid >> 5;
    const int lane = tid & 31;
    const int row0 = blockIdx.x * BM;

    // global-load assignment: A 512 float4 -> 4/thread, B 512 float4 -> 4/thread
    int arow[4], ac4[4];
#pragma unroll
    for (int j = 0; j < 4; j++) { int f = tid + j * NTHR; arow[j] = f >> 3; ac4[j] = f & 7; }

    float4 va[4], vb[4];

    // ---- prologue: stage 0 -> buf0 ----
#pragma unroll
    for (int j = 0; j < 4; j++) {
        va[j] = *(const float4*)(A + (size_t)(row0 + arow[j]) * H_DIM + ac4[j] * 4);
        vb[j] = *(const float4*)(W + (size_t)arow[j] * H_DIM + ac4[j] * 4);
    }
    {
        const uint32_t da = sbase, db = sbase + 2 * ATILE;
#pragma unroll
        for (int j = 0; j < 4; j++) {
            uint32_t h0, m0, h1, m1;
            const uint32_t off = (uint32_t)(arow[j] * PITCH + ac4[j] * 8);
            split2(va[j].x, va[j].y, h0, m0);
            split2(va[j].z, va[j].w, h1, m1);
            sts64(da + off, h0, h1);
            sts64(da + ATILE + off, m0, m1);
            split2(vb[j].x, vb[j].y, h0, m0);
            split2(vb[j].z, vb[j].w, h1, m1);
            sts64(db + off, h0, h1);
            sts64(db + BTILE + off, m0, m1);
        }
    }
    __syncthreads();
#pragma unroll
    for (int j = 0; j < 4; j++) {   // stage 1 into registers
        va[j] = *(const float4*)(A + (size_t)(row0 + arow[j]) * H_DIM + KC + ac4[j] * 4);
        vb[j] = *(const float4*)(W + (size_t)arow[j] * H_DIM + KC + ac4[j] * 4);
    }

    // warp tile 32x32: mbase = (wid&1)*32, nbase = (wid>>1)*32
    const int mbase = (wid & 1) * 32, nbase = (wid >> 1) * 32;
    const uint32_t a_off0 = (uint32_t)((mbase + (lane & 15)) * PITCH + (lane >> 4) * 16);
    const uint32_t b_off0 = (uint32_t)((nbase + (lane & 7) + ((lane >> 4) & 1) * 8) * PITCH
                                       + ((lane >> 3) & 1) * 16);

    float acc[32];
#pragma unroll
    for (int i = 0; i < 32; i++) acc[i] = 0.0f;

    for (int i = 0; i < NSTG; i++) {
        // producer: split regs (stage i+1) -> other buffer, then LDG stage i+2
        if (i + 1 < NSTG) {
            const uint32_t da = sbase + (uint32_t)((i + 1) & 1) * STG_B;
            const uint32_t db = da + 2 * ATILE;
#pragma unroll
            for (int j = 0; j < 4; j++) {
                uint32_t h0, m0, h1, m1;
                const uint32_t off = (uint32_t)(arow[j] * PITCH + ac4[j] * 8);
                split2(va[j].x, va[j].y, h0, m0);
                split2(va[j].z, va[j].w, h1, m1);
                sts64(da + off, h0, h1);
                sts64(da + ATILE + off, m0, m1);
                split2(vb[j].x, vb[j].y, h0, m0);
                split2(vb[j].z, vb[j].w, h1, m1);
                sts64(db + off, h0, h1);
                sts64(db + BTILE + off, m0, m1);
            }
            if (i + 2 < NSTG) {
                const int kt = (i + 2) * KC;
#pragma unroll
                for (int j = 0; j < 4; j++) {
                    va[j] = *(const float4*)(A + (size_t)(row0 + arow[j]) * H_DIM + kt + ac4[j] * 4);
                    vb[j] = *(const float4*)(W + (size_t)arow[j] * H_DIM + kt + ac4[j] * 4);
                }
            }
        }

        // consumer: LDSM + MMA on current buffer
        const uint32_t sa = sbase + (uint32_t)(i & 1) * STG_B;
        const uint32_t sb = sa + 2 * ATILE;
#pragma unroll
        for (int ks = 0; ks < 2; ks++) {
            uint32_t aF[2][2][4], bF[2][8];
#pragma unroll
            for (int L = 0; L < 2; L++)
#pragma unroll
                for (int mt = 0; mt < 2; mt++)
                    LDSM_X4(aF[L][mt][0], aF[L][mt][1], aF[L][mt][2], aF[L][mt][3],
                            sa + L * ATILE + a_off0 + (uint32_t)(mt * 16 * PITCH) + ks * 32);
#pragma unroll
            for (int L = 0; L < 2; L++)
#pragma unroll
                for (int np = 0; np < 2; np++)
                    LDSM_X4(bF[L][np * 4 + 0], bF[L][np * 4 + 1],
                            bF[L][np * 4 + 2], bF[L][np * 4 + 3],
                            sb + L * BTILE + b_off0 + (uint32_t)(np * 16 * PITCH) + ks * 32);
            // terms: hh, hm, mh (mm dropped, ~2^-22 rel)
#pragma unroll
            for (int mt = 0; mt < 2; mt++)
#pragma unroll
                for (int nt = 0; nt < 4; nt++) {
                    float* d = acc + (mt * 4 + nt) * 4;
                    MMA16816(d, aF[0][mt], bF[0] + nt * 2);
                    MMA16816(d, aF[0][mt], bF[1] + nt * 2);
                    MMA16816(d, aF[1][mt], bF[0] + nt * 2);
                }
        }
        __syncthreads();
    }

    // ---- fused epilogue ----
    float* fsm = (float*)dynsm;                 // [64][68]
    int*   si1 = (int*)(fsm + 64 * 68);
    float* sp1 = (float*)(si1 + 64);
    int*   si2 = (int*)(sp1 + 64);
    float* sp2 = (float*)(si2 + 64);

    {
#pragma unroll
        for (int mt = 0; mt < 2; mt++) {
            const int mrow = mbase + mt * 16 + (lane >> 2);
#pragma unroll
            for (int nt = 0; nt < 4; nt++) {
                const int ncol = nbase + nt * 8 + (lane & 3) * 2;
                float* d = acc + (mt * 4 + nt) * 4;
                *(float2*)&fsm[mrow * 68 + ncol] = make_float2(d[0], d[1]);
                *(float2*)&fsm[(mrow + 8) * 68 + ncol] = make_float2(d[2], d[3]);
            }
        }
    }
    __syncthreads();

    if (tid < BM) {
        float lg[64];
#pragma unroll
        for (int c = 0; c < 64; c++) lg[c] = fsm[tid * 68 + c];
        float mx = lg[0];
#pragma unroll
        for (int c = 1; c < 64; c++) mx = fmaxf(mx, lg[c]);
        float se = 0.0f;
#pragma unroll
        for (int c = 0; c < 64; c++) se += expf(lg[c] - mx);
        float v1 = -INFINITY; int i1 = 0;
#pragma unroll
        for (int c = 0; c < 64; c++)
            if (lg[c] > v1) { v1 = lg[c]; i1 = c; }
        float v2 = -INFINITY; int i2 = 0;
#pragma unroll
        for (int c = 0; c < 64; c++)
            if (c != i1 && lg[c] > v2) { v2 = lg[c]; i2 = c; }

        const float p1 = expf(v1 - mx) / se;
        const float p2 = expf(v2 - mx) / se;
        const float inv = 1.0f / (p1 + p2);
        const int t = row0 + tid;
        out[W_OFF + (size_t)t * 2 + 0] = p1 * inv;
        out[W_OFF + (size_t)t * 2 + 1] = p2 * inv;
        out[I_OFF + (size_t)t * 2 + 0] = (float)i1;
        out[I_OFF + (size_t)t * 2 + 1] = (float)i2;
        si1[tid] = i1; sp1[tid] = p1;
        si2[tid] = i2; sp2[tid] = p2;
    }
    __syncthreads();

#pragma unroll
    for (int j = 0; j < 8; j++) {           // coalesced logits store: 1024 float4
        int u = j * NTHR + tid, r = u >> 4, c4 = (u & 15) * 4;
        float4 v = *(float4*)&fsm[r * 68 + c4];
        *(float4*)&out[L_OFF + (size_t)(row0 + r) * 64 + c4] = v;
    }

    if (tid < E_DIM) {                       // deterministic per-block partials
        float s1 = 0.0f, s2 = 0.0f, cc = 0.0f;
        for (int r = 0; r < BM; r++) {
            float v = fsm[r * 68 + tid];
            s1 += v;
            s2 = fmaf(v, v, s2);
            if (si1[r] == tid) cc += sp1[r];
            if (si2[r] == tid) cc += sp2[r];
        }
        const int b = blockIdx.x;
        g_partials[(b * 3 + 0) * E_DIM + tid] = s1;
        g_partials[(b * 3 + 1) * E_DIM + tid] = s2;
        g_partials[(b * 3 + 2) * E_DIM + tid] = cc;
    }

    // ---- fused finalize: last block computes scalar losses ----
    __syncthreads();
    __threadfence();
    __shared__ int s_last;
    if (tid == 0) s_last = (atomicAdd(&g_done, 1) == NBLK - 1) ? 1 : 0;
    __syncthreads();
    if (!s_last) return;
    __threadfence();

    float* red = (float*)dynsm;              // [2][3][64]
    {
        const int g = tid >> 6, e = tid & 63;    // 2 groups x 128 blocks
        float s1 = 0.0f, s2 = 0.0f, c = 0.0f;
        for (int b = g * 128; b < g * 128 + 128; b++) {
            s1 += g_partials[(b * 3 + 0) * E_DIM + e];
            s2 += g_partials[(b * 3 + 1) * E_DIM + e];
            c  += g_partials[(b * 3 + 2) * E_DIM + e];
        }
        red[(g * 3 + 0) * 64 + e] = s1;
        red[(g * 3 + 1) * 64 + e] = s2;
        red[(g * 3 + 2) * 64 + e] = c;
    }
    __syncthreads();

    float* sv = red + 6 * 64;
    float* sf = sv + 64;
    if (tid < 64) {
        float s1 = 0.0f, s2 = 0.0f, c = 0.0f;
#pragma unroll
        for (int g = 0; g < 2; g++) {
            s1 += red[(g * 3 + 0) * 64 + tid];
            s2 += red[(g * 3 + 1) * 64 + tid];
            c  += red[(g * 3 + 2) * 64 + tid];
        }
        const float invT = 1.0f / (float)T_TOK;
        const float mean = s1 * invT;
        sv[tid] = s2 * invT - mean * mean;
        sf[tid] = c * invT;
    }
    __syncthreads();
    if (tid == 0) {
        float vsum = 0.0f, fsum = 0.0f;
        for (int i = 0; i < E_DIM; i++) { vsum += sv[i]; fsum += sf[i]; }
        out[Z_OFF] = (vsum / (float)E_DIM) * 0.001f;
        const float meanf = fsum / (float)E_DIM;
        float a2 = 0.0f;
        for (int i = 0; i < E_DIM; i++) {
            const float d = sf[i] - meanf;
            a2 = fmaf(d, d, a2);
        }
        out[LB_OFF] = (sqrtf(a2 / (float)(E_DIM - 1)) / (meanf + 1e-8f)) * 0.01f;
        g_done = 0;
    }
}

extern "C" void kernel_launch(void* const* d_in, const int* in_sizes, int n_in,
                              void* d_out, int out_size)
{
    const float* hs = (const float*)d_in[0];
    const float* W  = (const float*)d_in[1];
    if (n_in >= 2 && in_sizes[0] < in_sizes[1]) {
        const float* t = hs; hs = W; W = t;
    }
    float* out = (float*)d_out;
    cudaFuncSetAttribute(fused_router_kernel,
                         cudaFuncAttributeMaxDynamicSharedMemorySize, DYN_B);
    fused_router_kernel<<<NBLK, NTHR, DYN_B>>>(hs, W, out);
}